// round 4
// baseline (speedup 1.0000x reference)
#include <cuda_runtime.h>
#include <math.h>

typedef unsigned long long u64;
#define FULLMASK 0xffffffffu

// ---- f32x2 packed-math helpers (sm_100+ PTX) ----
__device__ __forceinline__ u64 pk2(float lo, float hi) {
    u64 r; asm("mov.b64 %0, {%1,%2};" : "=l"(r) : "f"(lo), "f"(hi)); return r;
}
__device__ __forceinline__ void upk2(u64 v, float &lo, float &hi) {
    asm("mov.b64 {%0,%1}, %2;" : "=f"(lo), "=f"(hi) : "l"(v));
}
__device__ __forceinline__ void ffma2(u64 &d, u64 a, u64 b) {
    asm("fma.rn.f32x2 %0, %1, %2, %0;" : "+l"(d) : "l"(a), "l"(b));
}
__device__ __forceinline__ u64 mul2(u64 a, u64 b) {
    u64 r; asm("mul.rn.f32x2 %0, %1, %2;" : "=l"(r) : "l"(a), "l"(b)); return r;
}
__device__ __forceinline__ void lds2(u64 &a, u64 &b, unsigned addr) {
    asm volatile("ld.shared.v2.u64 {%0,%1}, [%2];" : "=l"(a), "=l"(b) : "r"(addr));
}
__device__ __forceinline__ void sts2(unsigned addr, u64 a, u64 b) {
    asm volatile("st.shared.v2.u64 [%0], {%1,%2};" :: "r"(addr), "l"(a), "l"(b) : "memory");
}
__device__ __forceinline__ void cpasync16(unsigned saddr, const void* g) {
    asm volatile("cp.async.cg.shared.global [%0], [%1], 16;" :: "r"(saddr), "l"(g) : "memory");
}

// ---- geometry ----
static constexpr int ROWS     = 56;    // batch rows per CTA
static constexpr int THREADS  = 224;   // 4 threads per row
static constexpr int G_I      = 160;   // smem float stride per i   (mod32 = 0, uniform)
static constexpr int G_V      = 80;    // smem float stride per phys (mod32 = 16 -> conflict-free)
static constexpr int GBUF     = 64 * G_I;              // 10240 floats per site buffer
static constexpr int ENV_OFF  = 2 * GBUF;              // 20480
static constexpr int ENV_STR  = 72;                    // env row stride (floats)
static constexpr int CFG_OFF  = ENV_OFF + ROWS * ENV_STR;   // 24512
static constexpr int SMEM_FLOATS = CFG_OFF + ROWS * 8;      // 24960
static constexpr int SMEM_BYTES  = SMEM_FLOATS * 4;         // 99840 B

__global__ void __launch_bounds__(THREADS, 1)
mps_kernel(const int* __restrict__ cfg, const float* __restrict__ left,
           const float* __restrict__ bulk, const float* __restrict__ right,
           float* __restrict__ out, int B, int nbulk)
{
    extern __shared__ float smem[];
    const unsigned sbase = (unsigned)__cvta_generic_to_shared(smem);
    const int tid  = threadIdx.x;
    const int lane = tid & 31;
    const int warp = tid >> 5;
    const int s    = tid & 3;        // sub-lane within row group
    const int lr   = tid >> 2;       // local row 0..55
    const int grow = blockIdx.x * ROWS + lr;
    unsigned* cfgb = (unsigned*)(smem + CFG_OFF);

    // ---- pack per-row configuration bits (256 sites -> 8 words/row) ----
    for (int g = 0; g < 8; ++g) {
        int lrow = warp * 8 + g;
        int gr   = blockIdx.x * ROWS + lrow;
        #pragma unroll
        for (int wo = 0; wo < 8; ++wo) {
            int vv = 0;
            if (gr < B) vv = cfg[(size_t)gr * 256 + wo * 32 + lane] & 1;
            unsigned word = __ballot_sync(FULLMASK, vv);
            if (lane == 0) cfgb[lrow * 8 + wo] = word;
        }
    }
    __syncthreads();

    // ---- prefetch helper: bulk site -> padded smem buffer via cp.async ----
    auto prefetch = [&](int bulkIdx, int bi) {
        const float4* src = (const float4*)bulk + (size_t)bulkIdx * 2048;
        unsigned dbase = sbase + (unsigned)(bi * GBUF * 4);
        #pragma unroll
        for (int q = 0; q < 10; ++q) {
            int idx = tid + THREADS * q;
            if (idx < 2048) {
                unsigned off = (unsigned)((idx >> 5) * G_I + ((idx >> 4) & 1) * G_V
                                          + ((idx & 15) << 2)) << 2;
                cpasync16(dbase + off, src + idx);
            }
        }
        asm volatile("cp.async.commit_group;" ::: "memory");
    };

    prefetch(0, 0);   // site 1 -> buffer 0

    const unsigned envw = sbase + (unsigned)((ENV_OFF + lr * ENV_STR + 4 * s) * 4);
    const float*  envrow = smem + ENV_OFF + lr * ENV_STR;
    float ls = 0.f;

    // ---- init env from `left`, rescale, store to smem ----
    {
        int v0 = cfgb[lr * 8] & 1;
        float a[16];
        #pragma unroll
        for (int k = 0; k < 4; ++k)
            #pragma unroll
            for (int c = 0; c < 4; ++c)
                a[k * 4 + c] = left[v0 * 64 + 4 * s + 16 * k + c];
        float m = 0.f;
        #pragma unroll
        for (int x = 0; x < 16; ++x) m = fmaxf(m, fabsf(a[x]));
        m = fmaxf(m, __shfl_xor_sync(FULLMASK, m, 1));
        m = fmaxf(m, __shfl_xor_sync(FULLMASK, m, 2));
        m = fmaxf(m, 1e-30f);
        ls += logf(m);
        float inv = 1.0f / m;
        #pragma unroll
        for (int k = 0; k < 4; ++k)
            sts2(envw + 64u * k, pk2(a[4*k]*inv, a[4*k+1]*inv),
                                 pk2(a[4*k+2]*inv, a[4*k+3]*inv));
    }

    // ---- main chain over bulk sites ----
    #pragma unroll 1
    for (int tt = 1; tt <= nbulk; ++tt) {
        asm volatile("cp.async.wait_group 0;" ::: "memory");
        __syncthreads();
        if (tt < nbulk) prefetch(tt, tt & 1);

        const int v = (cfgb[lr * 8 + (tt >> 5)] >> (tt & 31)) & 1;
        const unsigned gb = sbase + (unsigned)((((tt - 1) & 1) * GBUF + v * G_V + 4 * s) * 4);

        u64 acc[8];
        #pragma unroll
        for (int p = 0; p < 8; ++p) acc[p] = 0ull;

        #define MSTEP(EV, II) { u64 ee = pk2((EV), (EV));                      \
            unsigned ga = gb + (unsigned)((II) * 640);                         \
            u64 g0, g1;                                                        \
            lds2(g0, g1, ga      ); ffma2(acc[0], ee, g0); ffma2(acc[1], ee, g1); \
            lds2(g0, g1, ga +  64u); ffma2(acc[2], ee, g0); ffma2(acc[3], ee, g1); \
            lds2(g0, g1, ga + 128u); ffma2(acc[4], ee, g0); ffma2(acc[5], ee, g1); \
            lds2(g0, g1, ga + 192u); ffma2(acc[6], ee, g0); ffma2(acc[7], ee, g1); }

        #pragma unroll
        for (int iv = 0; iv < 16; ++iv) {
            float4 e4 = *(const float4*)(envrow + 4 * iv);
            MSTEP(e4.x, 4 * iv + 0)
            MSTEP(e4.y, 4 * iv + 1)
            MSTEP(e4.z, 4 * iv + 2)
            MSTEP(e4.w, 4 * iv + 3)
        }
        #undef MSTEP

        // ---- rescale: group max, log accumulate, store scaled env ----
        float xf[16];
        #pragma unroll
        for (int p = 0; p < 8; ++p) upk2(acc[p], xf[2 * p], xf[2 * p + 1]);
        float m = 0.f;
        #pragma unroll
        for (int x = 0; x < 16; ++x) m = fmaxf(m, fabsf(xf[x]));
        m = fmaxf(m, __shfl_xor_sync(FULLMASK, m, 1));
        m = fmaxf(m, __shfl_xor_sync(FULLMASK, m, 2));
        m = fmaxf(m, 1e-30f);
        ls += logf(m);
        float inv = 1.0f / m;
        u64 inv2 = pk2(inv, inv);
        #pragma unroll
        for (int k = 0; k < 4; ++k)
            sts2(envw + 64u * k, mul2(acc[2 * k], inv2), mul2(acc[2 * k + 1], inv2));
    }

    // ---- final site: contract with `right`, emit log amplitude^2 ----
    {
        int lastbit = nbulk + 1;                       // site index 255
        int v = (cfgb[lr * 8 + (lastbit >> 5)] >> (lastbit & 31)) & 1;
        float p = 0.f;
        #pragma unroll
        for (int k = 0; k < 4; ++k) {
            float4 ev = *(const float4*)(envrow + 4 * s + 16 * k);
            int i0 = 4 * s + 16 * k;
            p += ev.x * right[(i0 + 0) * 2 + v];
            p += ev.y * right[(i0 + 1) * 2 + v];
            p += ev.z * right[(i0 + 2) * 2 + v];
            p += ev.w * right[(i0 + 3) * 2 + v];
        }
        p += __shfl_xor_sync(FULLMASK, p, 1);
        p += __shfl_xor_sync(FULLMASK, p, 2);
        if (s == 0 && grow < B) {
            float m2 = fmaxf(fabsf(p), 1e-30f);
            float pr = p / m2;
            float ab = fmaxf(pr * pr, 1e-30f);
            out[grow] = logf(ab) + 2.0f * (ls + logf(m2));
        }
    }
}

extern "C" void kernel_launch(void* const* d_in, const int* in_sizes, int n_in,
                              void* d_out, int out_size)
{
    const int*   cfg   = (const int*)d_in[0];
    const float* left  = (const float*)d_in[1];
    const float* bulk  = (const float*)d_in[2];
    const float* right = (const float*)d_in[3];
    float* out = (float*)d_out;

    int B     = in_sizes[0] / 256;          // 8192
    int nbulk = in_sizes[2] / (64 * 2 * 64); // 254
    int ncta  = (B + ROWS - 1) / ROWS;       // 147

    cudaFuncSetAttribute(mps_kernel, cudaFuncAttributeMaxDynamicSharedMemorySize, SMEM_BYTES);
    mps_kernel<<<ncta, THREADS, SMEM_BYTES>>>(cfg, left, bulk, right, out, B, nbulk);
}

// round 10
// speedup vs baseline: 1.6582x; 1.6582x over previous
#include <cuda_runtime.h>
#include <math.h>

typedef unsigned long long u64;
typedef unsigned char u8;
#define FULLMASK 0xffffffffu

// Transposed bulk scratch: [site][v][j][i], 256*8192 floats (8.4 MB)
__device__ float g_bulkT[256 * 8192];

// ---- PTX helpers ----
__device__ __forceinline__ void upk2(u64 v, float &lo, float &hi) {
    asm("mov.b64 {%0,%1}, %2;" : "=f"(lo), "=f"(hi) : "l"(v));
}
__device__ __forceinline__ void ffma2(u64 &d, u64 a, u64 b) {
    asm("fma.rn.f32x2 %0, %1, %2, %0;" : "+l"(d) : "l"(a), "l"(b));
}
__device__ __forceinline__ void lds2(u64 &a, u64 &b, unsigned addr) {
    asm volatile("ld.shared.v2.u64 {%0,%1}, [%2];" : "=l"(a), "=l"(b) : "r"(addr));
}
__device__ __forceinline__ void sts32(unsigned addr, float v) {
    asm volatile("st.shared.f32 [%0], %1;" :: "r"(addr), "f"(v) : "memory");
}
__device__ __forceinline__ void cpasync16(unsigned saddr, const void* g) {
    asm volatile("cp.async.cg.shared.global [%0], [%1], 16;" :: "r"(saddr), "l"(g) : "memory");
}

// ---- geometry ----
static constexpr int THREADS = 256;   // 8 warps = 8 row groups
static constexpr int ROWS    = 56;    // real batch rows per CTA
static constexpr int JS      = 68;    // padded j stride in floats (272B, 16B-aligned, conflict-free)
static constexpr int PLANE   = 64 * JS;       // 4352 floats per v-plane
static constexpr int GBUF    = 2 * PLANE;     // 8704 floats per site buffer
// smem float offsets
static constexpr int G_OFF    = 0;
static constexpr int ENV_OFF  = 2 * GBUF;           // 17408   (64 rows x 64 floats)
static constexpr int PERM_OFF = ENV_OFF + 4096;     // 21504   (256 sites x 64 bytes)
static constexpr int VW_OFF   = PERM_OFF + 4096;    // 25600   (256 sites x 2 words)
static constexpr int CFGB_OFF = VW_OFF + 512;       // 26112   (56 rows x 8 words)
static constexpr int LS_OFF   = CFGB_OFF + 448;     // 26560   (64 ints)
static constexpr int N0_OFF   = LS_OFF + 64;        // 26624   (256 bytes)
static constexpr int SMEM_FLOATS = N0_OFF + 64;     // 26688
static constexpr int SMEM_BYTES  = SMEM_FLOATS * 4; // 106752 B

// ---- one-time transpose: bulk[t][i][v][j] -> g_bulkT[t][v][j][i] ----
__global__ void __launch_bounds__(256)
transpose_bulk(const float* __restrict__ bulk)
{
    __shared__ float tb[64][65];
    int b = blockIdx.x; int ts = b >> 1, v = b & 1;
    const float* src = bulk + (size_t)ts * 8192 + v * 64;   // per-site stride = 64*2*64
    int tid = threadIdx.x;
    #pragma unroll
    for (int q = 0; q < 4; ++q) {
        int idx = tid + 256 * q;
        int i = idx >> 4, j4 = idx & 15;
        float4 val = *(const float4*)(src + i * 128 + j4 * 4);
        tb[i][j4 * 4 + 0] = val.x; tb[i][j4 * 4 + 1] = val.y;
        tb[i][j4 * 4 + 2] = val.z; tb[i][j4 * 4 + 3] = val.w;
    }
    __syncthreads();
    float* dst = g_bulkT + (size_t)ts * 8192 + v * 4096;
    #pragma unroll
    for (int q = 0; q < 4; ++q) {
        int idx = tid + 256 * q;
        int j = idx >> 4, i4 = idx & 15;
        float4 o;
        o.x = tb[i4 * 4 + 0][j]; o.y = tb[i4 * 4 + 1][j];
        o.z = tb[i4 * 4 + 2][j]; o.w = tb[i4 * 4 + 3][j];
        *(float4*)(dst + j * 64 + i4 * 4) = o;
    }
}

// ---- main kernel ----
__global__ void __launch_bounds__(THREADS, 1)
mps_main(const int* __restrict__ cfg, const float* __restrict__ left,
         const float* __restrict__ right, float* __restrict__ out,
         int B, int nbulk)
{
    extern __shared__ float smem[];
    const unsigned sbase = (unsigned)__cvta_generic_to_shared(smem);
    const int tid = threadIdx.x, lane = tid & 31, warp = tid >> 5;
    unsigned* cfgb = (unsigned*)(smem + CFGB_OFF);
    unsigned* vw   = (unsigned*)(smem + VW_OFF);
    u8*  permb     = (u8*)(smem + PERM_OFF);
    int* lsx       = (int*)(smem + LS_OFF);
    u8*  n0b       = (u8*)(smem + N0_OFF);
    float* env     = smem + ENV_OFF;

    auto prefetch = [&](int bIdx, int buf) {
        const float4* src = (const float4*)g_bulkT + (size_t)bIdx * 2048;
        unsigned dbase = sbase + (unsigned)(buf * GBUF * 4);
        #pragma unroll
        for (int q = 0; q < 8; ++q) {
            int idx = tid + 256 * q;          // 2048 16B chunks
            unsigned vj = (unsigned)idx >> 4, i4 = (unsigned)idx & 15;
            cpasync16(dbase + vj * (JS * 4) + i4 * 16, src + idx);
        }
        asm volatile("cp.async.commit_group;" ::: "memory");
    };

    prefetch(0, 0);   // overlap with setup phases

    // phase 1: pack row-major config bits (coalesced loads + ballot)
    for (int g = 0; g < 7; ++g) {
        int lrow = warp * 7 + g;
        int gr = blockIdx.x * ROWS + lrow;
        #pragma unroll
        for (int wo = 0; wo < 8; ++wo) {
            int vv = (gr < B) ? (cfg[(size_t)gr * 256 + wo * 32 + lane] & 1) : 0;
            unsigned word = __ballot_sync(FULLMASK, vv);
            if (lane == 0) cfgb[lrow * 8 + wo] = word;
        }
    }
    __syncthreads();

    // phase 2: transpose bits to site-major: vw[2t] = rows 0..31, vw[2t+1] = rows 32..55
    for (int q = 0; q < 32; ++q) {
        int t = warp * 32 + q;
        unsigned b0 = (cfgb[lane * 8 + (t >> 5)] >> (t & 31)) & 1;
        unsigned m0 = __ballot_sync(FULLMASK, b0);
        unsigned b1 = 0;
        if (lane < 24) b1 = (cfgb[(32 + lane) * 8 + (t >> 5)] >> (t & 31)) & 1;
        unsigned m1 = __ballot_sync(FULLMASK, b1);
        if (lane == 0) { vw[2 * t] = m0; vw[2 * t + 1] = m1; }
    }
    __syncthreads();

    // phase 3: per-site v-sorted permutation (8-row groups, dummy row 63 pads), env/ls init
    {
        int t = tid;
        unsigned w0 = vw[2 * t], w1 = vw[2 * t + 1] & 0xFFFFFFu;
        int k0 = 56 - __popc(w0) - __popc(w1);
        int n0 = (k0 + 7) >> 3;
        n0b[t] = (u8)n0;
        u8* pt = permb + t * 64;
        int i0 = 0, i1 = n0 * 8;
        for (int r = 0; r < 56; ++r) {
            int v = (r < 32) ? ((w0 >> r) & 1) : ((w1 >> (r - 32)) & 1);
            if (v) pt[i1++] = (u8)r; else pt[i0++] = (u8)r;
        }
        while (i0 < n0 * 8) pt[i0++] = 63;
        while (i1 < 64)     pt[i1++] = 63;

        if (tid < 64) lsx[tid] = 0;
        unsigned w00 = vw[0], w01 = vw[1];
        for (int idx = tid; idx < ROWS * 64; idx += 256) {
            int r = idx >> 6, i = idx & 63;
            int v0 = (r < 32) ? ((w00 >> r) & 1) : ((w01 >> (r - 32)) & 1);
            env[r * 64 + i] = left[v0 * 64 + i];
        }
        // dummy rows 56..63: zero-fill so their garbage can't make NaN/Inf traffic
        for (int idx = tid; idx < 8 * 64; idx += 256) {
            env[(56 + (idx >> 6)) * 64 + (idx & 63)] = 0.f;
        }
    }
    __syncthreads();

    // ---- main chain ----
    #pragma unroll 1
    for (int tt = 1; tt <= nbulk; ++tt) {
        asm volatile("cp.async.wait_group 0;" ::: "memory");
        __syncthreads();
        if (tt < nbulk) prefetch(tt, tt & 1);

        const int n0 = n0b[tt];
        const int v  = (warp >= n0) ? 1 : 0;
        u64 p8;
        {
            unsigned pa = sbase + (unsigned)(PERM_OFF * 4 + tt * 64 + warp * 8);
            asm volatile("ld.shared.b64 %0, [%1];" : "=l"(p8) : "r"(pa));
        }
        unsigned ea[8];
        #pragma unroll
        for (int k = 0; k < 8; ++k) {
            unsigned r = (unsigned)((p8 >> (8 * k)) & 0xFF);
            ea[k] = sbase + (unsigned)(ENV_OFF * 4) + r * 256u;
        }
        const unsigned gb0 = sbase
            + (unsigned)((G_OFF + ((tt - 1) & 1) * GBUF + v * PLANE) * 4)
            + (unsigned)lane * (JS * 4);
        const unsigned gb1 = gb0 + 32u * (JS * 4);

        u64 acc[16];
        #pragma unroll
        for (int p = 0; p < 16; ++p) acc[p] = 0ull;

        #pragma unroll
        for (int i4 = 0; i4 < 16; ++i4) {
            u64 ga0, ga1, gc0, gc1;
            lds2(ga0, ga1, gb0 + (unsigned)(i4 * 16));   // j = lane,    i..i+3
            lds2(gc0, gc1, gb1 + (unsigned)(i4 * 16));   // j = lane+32, i..i+3
            #pragma unroll
            for (int k = 0; k < 8; ++k) {
                u64 e0, e1;                               // broadcast: env[r_k][i..i+3]
                lds2(e0, e1, ea[k] + (unsigned)(i4 * 16));
                ffma2(acc[2 * k],     e0, ga0);
                ffma2(acc[2 * k],     e1, ga1);
                ffma2(acc[2 * k + 1], e0, gc0);
                ffma2(acc[2 * k + 1], e1, gc1);
            }
        }

        int myr = (int)((p8 >> (8 * (lane & 7))) & 0xFF);   // lane<8: its row for ls update
        #pragma unroll
        for (int k = 0; k < 8; ++k) {
            float a, b, c, d;
            upk2(acc[2 * k], a, b); upk2(acc[2 * k + 1], c, d);
            float h0 = a + b, h1 = c + d;
            float mm = fmaxf(fabsf(h0), fabsf(h1));
            mm = fmaxf(mm, __shfl_xor_sync(FULLMASK, mm, 1));
            mm = fmaxf(mm, __shfl_xor_sync(FULLMASK, mm, 2));
            mm = fmaxf(mm, __shfl_xor_sync(FULLMASK, mm, 4));
            mm = fmaxf(mm, __shfl_xor_sync(FULLMASK, mm, 8));
            mm = fmaxf(mm, __shfl_xor_sync(FULLMASK, mm, 16));
            mm = fmaxf(mm, 1e-30f);
            unsigned eb = (__float_as_uint(mm) >> 23) & 255u;   // power-of-2 rescale (exact)
            eb = eb > 253u ? 253u : eb;
            float inv = __uint_as_float((254u - eb) << 23);     // 2^-(eb-127)
            if (lane == k && myr < 63) lsx[myr] += (int)eb - 127;
            sts32(ea[k] + (unsigned)lane * 4u,        h0 * inv);
            sts32(ea[k] + 128u + (unsigned)lane * 4u, h1 * inv);
        }
    }
    __syncthreads();

    // ---- final site: contract with `right`, emit log ----
    if (warp < 7) {
        const int sidx = nbulk + 1;
        unsigned wv0 = vw[2 * sidx], wv1 = vw[2 * sidx + 1];
        float4 r4 = *(const float4*)(right + 4 * lane);   // (i=2l,v0),(2l,v1),(2l+1,v0),(2l+1,v1)
        #pragma unroll
        for (int k = 0; k < 8; ++k) {
            int r = warp * 8 + k;
            int v = (r < 32) ? ((wv0 >> r) & 1) : ((wv1 >> (r - 32)) & 1);
            float e0 = env[r * 64 + 2 * lane], e1 = env[r * 64 + 2 * lane + 1];
            float a = v ? r4.y : r4.x;
            float b = v ? r4.w : r4.z;
            float p = e0 * a + e1 * b;
            p += __shfl_xor_sync(FULLMASK, p, 1);
            p += __shfl_xor_sync(FULLMASK, p, 2);
            p += __shfl_xor_sync(FULLMASK, p, 4);
            p += __shfl_xor_sync(FULLMASK, p, 8);
            p += __shfl_xor_sync(FULLMASK, p, 16);
            if (lane == k) {
                int grow = blockIdx.x * ROWS + r;
                if (grow < B) {
                    float lsf = 0.69314718055994531f * (float)lsx[r];
                    float m2 = fmaxf(fabsf(p), 1e-30f);
                    float pr = p / m2;
                    float ab = fmaxf(pr * pr, 1e-30f);
                    out[grow] = logf(ab) + 2.0f * (lsf + logf(m2));
                }
            }
        }
    }
}

extern "C" void kernel_launch(void* const* d_in, const int* in_sizes, int n_in,
                              void* d_out, int out_size)
{
    const int*   cfg   = (const int*)d_in[0];
    const float* left  = (const float*)d_in[1];
    const float* bulk  = (const float*)d_in[2];
    const float* right = (const float*)d_in[3];
    float* out = (float*)d_out;

    int B     = in_sizes[0] / 256;            // 8192
    int nbulk = in_sizes[2] / (64 * 2 * 64);  // 254
    int ncta  = (B + ROWS - 1) / ROWS;        // 147

    transpose_bulk<<<nbulk * 2, 256>>>(bulk);
    cudaFuncSetAttribute(mps_main, cudaFuncAttributeMaxDynamicSharedMemorySize, SMEM_BYTES);
    mps_main<<<ncta, THREADS, SMEM_BYTES>>>(cfg, left, right, out, B, nbulk);
}

// round 15
// speedup vs baseline: 1.9101x; 1.1519x over previous
#include <cuda_runtime.h>
#include <math.h>

typedef unsigned long long u64;
typedef unsigned char u8;
#define FULLMASK 0xffffffffu

// Transposed+pre-swizzled bulk scratch: [site][v][ih][j][i32], 254*8192 floats (8.3 MB)
// Byte offset within a site's 32KB block is stored XOR-swizzled: S(L)=L^((L>>3)&0x70)
__device__ float g_bulkT[256 * 8192];

// ---- PTX helpers ----
__device__ __forceinline__ void upk2(u64 v, float &lo, float &hi) {
    asm("mov.b64 {%0,%1}, %2;" : "=f"(lo), "=f"(hi) : "l"(v));
}
__device__ __forceinline__ void ffma2(u64 &d, u64 a, u64 b) {
    asm("fma.rn.f32x2 %0, %1, %2, %0;" : "+l"(d) : "l"(a), "l"(b));
}
__device__ __forceinline__ void lds2(u64 &a, u64 &b, unsigned addr) {
    asm volatile("ld.shared.v2.u64 {%0,%1}, [%2];" : "=l"(a), "=l"(b) : "r"(addr));
}
__device__ __forceinline__ void sts32(unsigned addr, float v) {
    asm volatile("st.shared.f32 [%0], %1;" :: "r"(addr), "f"(v) : "memory");
}

// ---- geometry ----
static constexpr int THREADS = 256;   // 8 warps = 8 row groups
static constexpr int ROWS    = 56;    // real batch rows per CTA
// smem float offsets
static constexpr int G_OFF    = 0;                  // 2 x 8192 floats (two 32KB site buffers)
static constexpr int ENV_OFF  = 16384;              // 64 rows x 64 floats
static constexpr int PERM_OFF = ENV_OFF + 4096;     // 20480: 256 sites x 64 bytes
static constexpr int VW_OFF   = PERM_OFF + 4096;    // 24576: 256 sites x 2 words
static constexpr int CFGB_OFF = VW_OFF + 512;       // 25088: 56 rows x 8 words
static constexpr int LS_OFF   = CFGB_OFF + 448;     // 25536: 64 ints
static constexpr int N0_OFF   = LS_OFF + 64;        // 25600: 256 bytes
static constexpr int MBAR_OFF = N0_OFF + 64;        // 25664: 2 mbarriers (16B)
static constexpr int SMEM_FLOATS = MBAR_OFF + 8;    // 25672
static constexpr int SMEM_BYTES  = SMEM_FLOATS * 4; // 102688 B

// ---- one-time transpose: bulk[t][i][v][j] -> swizzled g_bulkT[t][v][ih][j][i32] ----
__global__ void __launch_bounds__(256)
transpose_bulk(const float* __restrict__ bulk)
{
    __shared__ float tb[64][65];
    int b = blockIdx.x; int ts = b >> 1, v = b & 1;
    const float* src = bulk + (size_t)ts * 8192 + v * 64;   // per-site stride 64*2*64
    int tid = threadIdx.x;
    #pragma unroll
    for (int q = 0; q < 4; ++q) {
        int idx = tid + 256 * q;
        int i = idx >> 4, j4 = idx & 15;
        float4 val = *(const float4*)(src + i * 128 + j4 * 4);
        tb[i][j4 * 4 + 0] = val.x; tb[i][j4 * 4 + 1] = val.y;
        tb[i][j4 * 4 + 2] = val.z; tb[i][j4 * 4 + 3] = val.w;
    }
    __syncthreads();
    char* dstSite = (char*)(g_bulkT + (size_t)ts * 8192);
    #pragma unroll
    for (int q = 0; q < 4; ++q) {
        int idx = tid + 256 * q;           // 1024 16B chunks per (site,v)
        int ih = idx >> 9, j = (idx >> 3) & 63, c = idx & 7;
        float4 o;
        o.x = tb[ih * 32 + c * 4 + 0][j];
        o.y = tb[ih * 32 + c * 4 + 1][j];
        o.z = tb[ih * 32 + c * 4 + 2][j];
        o.w = tb[ih * 32 + c * 4 + 3][j];
        unsigned L = (unsigned)((v * 2 + ih) * 8192 + j * 128 + c * 16);
        unsigned S = L ^ ((L >> 3) & 0x70u);      // SW128-style swizzle, baked into gmem
        *(float4*)(dstSite + S) = o;
    }
}

// ---- main kernel ----
__global__ void __launch_bounds__(THREADS, 1)
mps_main(const int* __restrict__ cfg, const float* __restrict__ left,
         const float* __restrict__ right, float* __restrict__ out,
         int B, int nbulk)
{
    extern __shared__ float smem[];
    const unsigned sbase = (unsigned)__cvta_generic_to_shared(smem);
    const int tid = threadIdx.x, lane = tid & 31, warp = tid >> 5;
    unsigned* cfgb = (unsigned*)(smem + CFGB_OFF);
    unsigned* vw   = (unsigned*)(smem + VW_OFF);
    u8*  permb     = (u8*)(smem + PERM_OFF);
    int* lsx       = (int*)(smem + LS_OFF);
    u8*  n0b       = (u8*)(smem + N0_OFF);
    float* env     = smem + ENV_OFF;
    const unsigned mbar0 = sbase + (unsigned)(MBAR_OFF * 4);

    auto issue_site = [&](int k) {    // tid 0 only: bulk-copy site k -> buffer k&1
        unsigned mb  = mbar0 + (unsigned)((k & 1) * 8);
        unsigned dst = sbase + (unsigned)((k & 1) * 32768);
        const char* src = (const char*)g_bulkT + (size_t)k * 32768;
        asm volatile("mbarrier.arrive.expect_tx.shared.b64 _, [%0], %1;"
                     :: "r"(mb), "r"(32768u) : "memory");
        asm volatile("cp.async.bulk.shared::cluster.global.mbarrier::complete_tx::bytes "
                     "[%0], [%1], %2, [%3];"
                     :: "r"(dst), "l"(src), "r"(32768u), "r"(mb) : "memory");
    };

    if (tid == 0) {
        asm volatile("mbarrier.init.shared.b64 [%0], 1;" :: "r"(mbar0) : "memory");
        asm volatile("mbarrier.init.shared.b64 [%0], 1;" :: "r"(mbar0 + 8u) : "memory");
        asm volatile("fence.proxy.async.shared::cta;" ::: "memory");
        issue_site(0);
    }

    // phase 1: pack row-major config bits (coalesced loads + ballot)
    for (int g = 0; g < 7; ++g) {
        int lrow = warp * 7 + g;
        int gr = blockIdx.x * ROWS + lrow;
        #pragma unroll
        for (int wo = 0; wo < 8; ++wo) {
            int vv = (gr < B) ? (cfg[(size_t)gr * 256 + wo * 32 + lane] & 1) : 0;
            unsigned word = __ballot_sync(FULLMASK, vv);
            if (lane == 0) cfgb[lrow * 8 + wo] = word;
        }
    }
    __syncthreads();

    // phase 2: transpose bits to site-major
    for (int q = 0; q < 32; ++q) {
        int t = warp * 32 + q;
        unsigned b0 = (cfgb[lane * 8 + (t >> 5)] >> (t & 31)) & 1;
        unsigned m0 = __ballot_sync(FULLMASK, b0);
        unsigned b1 = 0;
        if (lane < 24) b1 = (cfgb[(32 + lane) * 8 + (t >> 5)] >> (t & 31)) & 1;
        unsigned m1 = __ballot_sync(FULLMASK, b1);
        if (lane == 0) { vw[2 * t] = m0; vw[2 * t + 1] = m1; }
    }
    __syncthreads();

    // phase 3: per-site v-sorted permutation (8-row groups, dummy row 63 pads), env/ls init
    {
        int t = tid;
        unsigned w0 = vw[2 * t], w1 = vw[2 * t + 1] & 0xFFFFFFu;
        int k0 = 56 - __popc(w0) - __popc(w1);
        int n0 = (k0 + 7) >> 3;
        n0b[t] = (u8)n0;
        u8* pt = permb + t * 64;
        int i0 = 0, i1 = n0 * 8;
        for (int r = 0; r < 56; ++r) {
            int v = (r < 32) ? ((w0 >> r) & 1) : ((w1 >> (r - 32)) & 1);
            if (v) pt[i1++] = (u8)r; else pt[i0++] = (u8)r;
        }
        while (i0 < n0 * 8) pt[i0++] = 63;
        while (i1 < 64)     pt[i1++] = 63;

        if (tid < 64) lsx[tid] = 0;
        unsigned w00 = vw[0], w01 = vw[1];
        for (int idx = tid; idx < ROWS * 64; idx += 256) {
            int r = idx >> 6, i = idx & 63;
            int v0 = (r < 32) ? ((w00 >> r) & 1) : ((w01 >> (r - 32)) & 1);
            env[r * 64 + i] = left[v0 * 64 + i];
        }
        for (int idx = tid; idx < 8 * 64; idx += 256) {
            env[(56 + (idx >> 6)) * 64 + (idx & 63)] = 0.f;
        }
    }
    __syncthreads();

    // ---- main chain: step tt consumes G site k = tt-1 ----
    #pragma unroll 1
    for (int tt = 1; tt <= nbulk; ++tt) {
        const int k = tt - 1;
        {   // wait for buffer k&1, parity (k>>1)&1 (acquire)
            unsigned mb = mbar0 + (unsigned)((k & 1) * 8);
            unsigned ph = ((unsigned)k >> 1) & 1u;
            unsigned done;
            asm volatile("{\n\t.reg .pred p;\n\t"
                         "mbarrier.try_wait.parity.acquire.cta.shared::cta.b64 p, [%1], %2;\n\t"
                         "selp.b32 %0, 1, 0, p;\n\t}"
                         : "=r"(done) : "r"(mb), "r"(ph) : "memory");
            if (!done) {
                asm volatile("{\n\t.reg .pred P1;\n"
                             "WL_%=:\n\t"
                             "mbarrier.try_wait.parity.acquire.cta.shared::cta.b64 P1, [%0], %1, 0x989680;\n\t"
                             "@P1 bra.uni WD_%=;\n\t"
                             "bra.uni WL_%=;\n"
                             "WD_%=:\n\t}"
                             :: "r"(mb), "r"(ph) : "memory");
            }
        }
        __syncthreads();                       // all warps done with buffer (k+1)&1
        if (tid == 0 && k + 1 < nbulk) issue_site(k + 1);

        const int n0 = n0b[tt];
        const int v  = (warp >= n0) ? 1 : 0;
        u64 p8;
        {
            unsigned pa = sbase + (unsigned)(PERM_OFF * 4 + tt * 64 + warp * 8);
            asm volatile("ld.shared.b64 %0, [%1];" : "=l"(p8) : "r"(pa));
        }
        unsigned ea[8];
        #pragma unroll
        for (int kk = 0; kk < 8; ++kk) {
            unsigned r = (unsigned)((p8 >> (8 * kk)) & 0xFF);
            ea[kk] = sbase + (unsigned)(ENV_OFF * 4) + r * 256u;
        }
        const unsigned gb = sbase + (unsigned)((k & 1) * 32768 + v * 16384)
                          + (unsigned)lane * 128u;
        const unsigned xr = ((unsigned)lane & 7u) << 4;

        u64 acc[16];
        #pragma unroll
        for (int p = 0; p < 16; ++p) acc[p] = 0ull;

        #pragma unroll
        for (int i4 = 0; i4 < 16; ++i4) {
            int ih = i4 >> 3, c8 = i4 & 7;
            unsigned goff = (unsigned)(ih * 8192) + (((unsigned)c8 * 16u) ^ xr);
            u64 ga0, ga1, gc0, gc1;
            lds2(ga0, ga1, gb + goff);            // j = lane,    i..i+3
            lds2(gc0, gc1, gb + 4096u + goff);    // j = lane+32, i..i+3
            #pragma unroll
            for (int kk = 0; kk < 8; ++kk) {
                u64 e0, e1;                        // broadcast: env[r_kk][i..i+3]
                lds2(e0, e1, ea[kk] + (unsigned)(i4 * 16));
                ffma2(acc[2 * kk],     e0, ga0);
                ffma2(acc[2 * kk],     e1, ga1);
                ffma2(acc[2 * kk + 1], e0, gc0);
                ffma2(acc[2 * kk + 1], e1, gc1);
            }
        }

        int myr = (int)((p8 >> (8 * (lane & 7))) & 0xFF);   // lane<8: its row for ls update
        #pragma unroll
        for (int kk = 0; kk < 8; ++kk) {
            float a, b, c, d;
            upk2(acc[2 * kk], a, b); upk2(acc[2 * kk + 1], c, d);
            float h0 = a + b, h1 = c + d;
            unsigned mu = __float_as_uint(fmaxf(fabsf(h0), fabsf(h1)));
            unsigned mr;
            asm("redux.sync.max.u32 %0, %1, 0xffffffff;" : "=r"(mr) : "r"(mu));
            float mm = fmaxf(__uint_as_float(mr), 1e-30f);
            unsigned eb = (__float_as_uint(mm) >> 23) & 255u;   // power-of-2 rescale (exact)
            eb = eb > 253u ? 253u : eb;
            float inv = __uint_as_float((254u - eb) << 23);     // 2^-(eb-127)
            if (lane == kk && myr < 63) lsx[myr] += (int)eb - 127;
            sts32(ea[kk] + (unsigned)lane * 4u,        h0 * inv);
            sts32(ea[kk] + 128u + (unsigned)lane * 4u, h1 * inv);
        }
    }
    __syncthreads();

    // ---- final site: contract with `right`, emit log ----
    if (warp < 7) {
        const int sidx = nbulk + 1;
        unsigned wv0 = vw[2 * sidx], wv1 = vw[2 * sidx + 1];
        float4 r4 = *(const float4*)(right + 4 * lane);
        #pragma unroll
        for (int kk = 0; kk < 8; ++kk) {
            int r = warp * 8 + kk;
            int v = (r < 32) ? ((wv0 >> r) & 1) : ((wv1 >> (r - 32)) & 1);
            float e0 = env[r * 64 + 2 * lane], e1 = env[r * 64 + 2 * lane + 1];
            float a = v ? r4.y : r4.x;
            float b = v ? r4.w : r4.z;
            float p = e0 * a + e1 * b;
            p += __shfl_xor_sync(FULLMASK, p, 1);
            p += __shfl_xor_sync(FULLMASK, p, 2);
            p += __shfl_xor_sync(FULLMASK, p, 4);
            p += __shfl_xor_sync(FULLMASK, p, 8);
            p += __shfl_xor_sync(FULLMASK, p, 16);
            if (lane == kk) {
                int grow = blockIdx.x * ROWS + r;
                if (grow < B) {
                    float lsf = 0.69314718055994531f * (float)lsx[r];
                    float m2 = fmaxf(fabsf(p), 1e-30f);
                    float pr = p / m2;
                    float ab = fmaxf(pr * pr, 1e-30f);
                    out[grow] = logf(ab) + 2.0f * (lsf + logf(m2));
                }
            }
        }
    }
}

extern "C" void kernel_launch(void* const* d_in, const int* in_sizes, int n_in,
                              void* d_out, int out_size)
{
    const int*   cfg   = (const int*)d_in[0];
    const float* left  = (const float*)d_in[1];
    const float* bulk  = (const float*)d_in[2];
    const float* right = (const float*)d_in[3];
    float* out = (float*)d_out;

    int B     = in_sizes[0] / 256;            // 8192
    int nbulk = in_sizes[2] / (64 * 2 * 64);  // 254
    int ncta  = (B + ROWS - 1) / ROWS;        // 147

    transpose_bulk<<<nbulk * 2, 256>>>(bulk);
    cudaFuncSetAttribute(mps_main, cudaFuncAttributeMaxDynamicSharedMemorySize, SMEM_BYTES);
    mps_main<<<ncta, THREADS, SMEM_BYTES>>>(cfg, left, right, out, B, nbulk);
}

// round 16
// speedup vs baseline: 1.9106x; 1.0003x over previous
#include <cuda_runtime.h>
#include <math.h>

typedef unsigned long long u64;
typedef unsigned char u8;
#define FULLMASK 0xffffffffu

// Transposed+pre-swizzled bulk scratch: [site][v][ih][j][i32], 254*8192 floats (8.3 MB)
// Byte offset within a site's 32KB block is stored XOR-swizzled: S(L)=L^((L>>3)&0x70)
__device__ float g_bulkT[256 * 8192];

// ---- PTX helpers ----
__device__ __forceinline__ void upk2(u64 v, float &lo, float &hi) {
    asm("mov.b64 {%0,%1}, %2;" : "=f"(lo), "=f"(hi) : "l"(v));
}
__device__ __forceinline__ void ffma2(u64 &d, u64 a, u64 b) {
    asm("fma.rn.f32x2 %0, %1, %2, %0;" : "+l"(d) : "l"(a), "l"(b));
}
__device__ __forceinline__ void lds2(u64 &a, u64 &b, unsigned addr) {
    asm volatile("ld.shared.v2.u64 {%0,%1}, [%2];" : "=l"(a), "=l"(b) : "r"(addr));
}
__device__ __forceinline__ void sts32(unsigned addr, float v) {
    asm volatile("st.shared.f32 [%0], %1;" :: "r"(addr), "f"(v) : "memory");
}

// ---- geometry ----
static constexpr int THREADS = 256;   // 8 warps = 8 row groups
static constexpr int ROWS    = 56;    // real batch rows per CTA
// smem float offsets
static constexpr int G_OFF    = 0;                  // 2 x 8192 floats (two 32KB site buffers)
static constexpr int ENV_OFF  = 16384;              // 64 rows x 64 floats
static constexpr int PERM_OFF = ENV_OFF + 4096;     // 20480: 256 sites x 64 bytes
static constexpr int VW_OFF   = PERM_OFF + 4096;    // 24576: 256 sites x 2 words
static constexpr int CFGB_OFF = VW_OFF + 512;       // 25088: 56 rows x 8 words
static constexpr int LS_OFF   = CFGB_OFF + 448;     // 25536: 64 ints
static constexpr int N0_OFF   = LS_OFF + 64;        // 25600: 256 bytes
static constexpr int MBAR_OFF = N0_OFF + 64;        // 25664: 2 mbarriers (16B)
static constexpr int SMEM_FLOATS = MBAR_OFF + 8;    // 25672
static constexpr int SMEM_BYTES  = SMEM_FLOATS * 4; // 102688 B

// ---- one-time transpose: bulk[t][i][v][j] -> swizzled g_bulkT[t][v][ih][j][i32] ----
__global__ void __launch_bounds__(256)
transpose_bulk(const float* __restrict__ bulk)
{
    __shared__ float tb[64][65];
    int b = blockIdx.x; int ts = b >> 1, v = b & 1;
    const float* src = bulk + (size_t)ts * 8192 + v * 64;   // per-site stride 64*2*64
    int tid = threadIdx.x;
    #pragma unroll
    for (int q = 0; q < 4; ++q) {
        int idx = tid + 256 * q;
        int i = idx >> 4, j4 = idx & 15;
        float4 val = *(const float4*)(src + i * 128 + j4 * 4);
        tb[i][j4 * 4 + 0] = val.x; tb[i][j4 * 4 + 1] = val.y;
        tb[i][j4 * 4 + 2] = val.z; tb[i][j4 * 4 + 3] = val.w;
    }
    __syncthreads();
    char* dstSite = (char*)(g_bulkT + (size_t)ts * 8192);
    #pragma unroll
    for (int q = 0; q < 4; ++q) {
        int idx = tid + 256 * q;           // 1024 16B chunks per (site,v)
        int ih = idx >> 9, j = (idx >> 3) & 63, c = idx & 7;
        float4 o;
        o.x = tb[ih * 32 + c * 4 + 0][j];
        o.y = tb[ih * 32 + c * 4 + 1][j];
        o.z = tb[ih * 32 + c * 4 + 2][j];
        o.w = tb[ih * 32 + c * 4 + 3][j];
        unsigned L = (unsigned)((v * 2 + ih) * 8192 + j * 128 + c * 16);
        unsigned S = L ^ ((L >> 3) & 0x70u);      // SW128-style swizzle, baked into gmem
        *(float4*)(dstSite + S) = o;
    }
}

// ---- main kernel ----
__global__ void __launch_bounds__(THREADS, 1)
mps_main(const int* __restrict__ cfg, const float* __restrict__ left,
         const float* __restrict__ right, float* __restrict__ out,
         int B, int nbulk)
{
    extern __shared__ float smem[];
    const unsigned sbase = (unsigned)__cvta_generic_to_shared(smem);
    const int tid = threadIdx.x, lane = tid & 31, warp = tid >> 5;
    unsigned* cfgb = (unsigned*)(smem + CFGB_OFF);
    unsigned* vw   = (unsigned*)(smem + VW_OFF);
    u8*  permb     = (u8*)(smem + PERM_OFF);
    int* lsx       = (int*)(smem + LS_OFF);
    u8*  n0b       = (u8*)(smem + N0_OFF);
    float* env     = smem + ENV_OFF;
    const unsigned mbar0 = sbase + (unsigned)(MBAR_OFF * 4);

    auto issue_site = [&](int k) {    // tid 0 only: bulk-copy site k -> buffer k&1
        unsigned mb  = mbar0 + (unsigned)((k & 1) * 8);
        unsigned dst = sbase + (unsigned)((k & 1) * 32768);
        const char* src = (const char*)g_bulkT + (size_t)k * 32768;
        asm volatile("mbarrier.arrive.expect_tx.shared.b64 _, [%0], %1;"
                     :: "r"(mb), "r"(32768u) : "memory");
        asm volatile("cp.async.bulk.shared::cluster.global.mbarrier::complete_tx::bytes "
                     "[%0], [%1], %2, [%3];"
                     :: "r"(dst), "l"(src), "r"(32768u), "r"(mb) : "memory");
    };

    if (tid == 0) {
        asm volatile("mbarrier.init.shared.b64 [%0], 1;" :: "r"(mbar0) : "memory");
        asm volatile("mbarrier.init.shared.b64 [%0], 1;" :: "r"(mbar0 + 8u) : "memory");
        asm volatile("fence.proxy.async.shared::cta;" ::: "memory");
        issue_site(0);
    }

    // phase 1: pack row-major config bits (coalesced loads + ballot)
    for (int g = 0; g < 7; ++g) {
        int lrow = warp * 7 + g;
        int gr = blockIdx.x * ROWS + lrow;
        #pragma unroll
        for (int wo = 0; wo < 8; ++wo) {
            int vv = (gr < B) ? (cfg[(size_t)gr * 256 + wo * 32 + lane] & 1) : 0;
            unsigned word = __ballot_sync(FULLMASK, vv);
            if (lane == 0) cfgb[lrow * 8 + wo] = word;
        }
    }
    __syncthreads();

    // phase 2: transpose bits to site-major
    for (int q = 0; q < 32; ++q) {
        int t = warp * 32 + q;
        unsigned b0 = (cfgb[lane * 8 + (t >> 5)] >> (t & 31)) & 1;
        unsigned m0 = __ballot_sync(FULLMASK, b0);
        unsigned b1 = 0;
        if (lane < 24) b1 = (cfgb[(32 + lane) * 8 + (t >> 5)] >> (t & 31)) & 1;
        unsigned m1 = __ballot_sync(FULLMASK, b1);
        if (lane == 0) { vw[2 * t] = m0; vw[2 * t + 1] = m1; }
    }
    __syncthreads();

    // phase 3: per-site v-sorted permutation (8-row groups, dummy row 63 pads), env/ls init
    {
        int t = tid;
        unsigned w0 = vw[2 * t], w1 = vw[2 * t + 1] & 0xFFFFFFu;
        int k0 = 56 - __popc(w0) - __popc(w1);
        int n0 = (k0 + 7) >> 3;
        n0b[t] = (u8)n0;
        u8* pt = permb + t * 64;
        int i0 = 0, i1 = n0 * 8;
        for (int r = 0; r < 56; ++r) {
            int v = (r < 32) ? ((w0 >> r) & 1) : ((w1 >> (r - 32)) & 1);
            if (v) pt[i1++] = (u8)r; else pt[i0++] = (u8)r;
        }
        while (i0 < n0 * 8) pt[i0++] = 63;
        while (i1 < 64)     pt[i1++] = 63;

        if (tid < 64) lsx[tid] = 0;
        unsigned w00 = vw[0], w01 = vw[1];
        for (int idx = tid; idx < ROWS * 64; idx += 256) {
            int r = idx >> 6, i = idx & 63;
            int v0 = (r < 32) ? ((w00 >> r) & 1) : ((w01 >> (r - 32)) & 1);
            env[r * 64 + i] = left[v0 * 64 + i];
        }
        for (int idx = tid; idx < 8 * 64; idx += 256) {
            env[(56 + (idx >> 6)) * 64 + (idx & 63)] = 0.f;
        }
    }
    __syncthreads();

    // ---- main chain: step tt consumes G site k = tt-1 ----
    #pragma unroll 1
    for (int tt = 1; tt <= nbulk; ++tt) {
        const int k = tt - 1;
        {   // wait for buffer k&1, parity (k>>1)&1 (acquire)
            unsigned mb = mbar0 + (unsigned)((k & 1) * 8);
            unsigned ph = ((unsigned)k >> 1) & 1u;
            unsigned done;
            asm volatile("{\n\t.reg .pred p;\n\t"
                         "mbarrier.try_wait.parity.acquire.cta.shared::cta.b64 p, [%1], %2;\n\t"
                         "selp.b32 %0, 1, 0, p;\n\t}"
                         : "=r"(done) : "r"(mb), "r"(ph) : "memory");
            if (!done) {
                asm volatile("{\n\t.reg .pred P1;\n"
                             "WL_%=:\n\t"
                             "mbarrier.try_wait.parity.acquire.cta.shared::cta.b64 P1, [%0], %1, 0x989680;\n\t"
                             "@P1 bra.uni WD_%=;\n\t"
                             "bra.uni WL_%=;\n"
                             "WD_%=:\n\t}"
                             :: "r"(mb), "r"(ph) : "memory");
            }
        }
        __syncthreads();                       // all warps done with buffer (k+1)&1
        if (tid == 0 && k + 1 < nbulk) issue_site(k + 1);

        const int n0 = n0b[tt];
        const int v  = (warp >= n0) ? 1 : 0;
        u64 p8;
        {
            unsigned pa = sbase + (unsigned)(PERM_OFF * 4 + tt * 64 + warp * 8);
            asm volatile("ld.shared.b64 %0, [%1];" : "=l"(p8) : "r"(pa));
        }
        unsigned ea[8];
        #pragma unroll
        for (int kk = 0; kk < 8; ++kk) {
            unsigned r = (unsigned)((p8 >> (8 * kk)) & 0xFF);
            ea[kk] = sbase + (unsigned)(ENV_OFF * 4) + r * 256u;
        }
        const unsigned gb = sbase + (unsigned)((k & 1) * 32768 + v * 16384)
                          + (unsigned)lane * 128u;
        const unsigned xr = ((unsigned)lane & 7u) << 4;

        u64 acc[16];
        #pragma unroll
        for (int p = 0; p < 16; ++p) acc[p] = 0ull;

        #pragma unroll
        for (int i4 = 0; i4 < 16; ++i4) {
            int ih = i4 >> 3, c8 = i4 & 7;
            unsigned goff = (unsigned)(ih * 8192) + (((unsigned)c8 * 16u) ^ xr);
            u64 ga0, ga1, gc0, gc1;
            lds2(ga0, ga1, gb + goff);            // j = lane,    i..i+3
            lds2(gc0, gc1, gb + 4096u + goff);    // j = lane+32, i..i+3
            #pragma unroll
            for (int kk = 0; kk < 8; ++kk) {
                u64 e0, e1;                        // broadcast: env[r_kk][i..i+3]
                lds2(e0, e1, ea[kk] + (unsigned)(i4 * 16));
                ffma2(acc[2 * kk],     e0, ga0);
                ffma2(acc[2 * kk],     e1, ga1);
                ffma2(acc[2 * kk + 1], e0, gc0);
                ffma2(acc[2 * kk + 1], e1, gc1);
            }
        }

        int myr = (int)((p8 >> (8 * (lane & 7))) & 0xFF);   // lane<8: its row for ls update
        #pragma unroll
        for (int kk = 0; kk < 8; ++kk) {
            float a, b, c, d;
            upk2(acc[2 * kk], a, b); upk2(acc[2 * kk + 1], c, d);
            float h0 = a + b, h1 = c + d;
            unsigned mu = __float_as_uint(fmaxf(fabsf(h0), fabsf(h1)));
            unsigned mr;
            asm("redux.sync.max.u32 %0, %1, 0xffffffff;" : "=r"(mr) : "r"(mu));
            float mm = fmaxf(__uint_as_float(mr), 1e-30f);
            unsigned eb = (__float_as_uint(mm) >> 23) & 255u;   // power-of-2 rescale (exact)
            eb = eb > 253u ? 253u : eb;
            float inv = __uint_as_float((254u - eb) << 23);     // 2^-(eb-127)
            if (lane == kk && myr < 63) lsx[myr] += (int)eb - 127;
            sts32(ea[kk] + (unsigned)lane * 4u,        h0 * inv);
            sts32(ea[kk] + 128u + (unsigned)lane * 4u, h1 * inv);
        }
    }
    __syncthreads();

    // ---- final site: contract with `right`, emit log ----
    if (warp < 7) {
        const int sidx = nbulk + 1;
        unsigned wv0 = vw[2 * sidx], wv1 = vw[2 * sidx + 1];
        float4 r4 = *(const float4*)(right + 4 * lane);
        #pragma unroll
        for (int kk = 0; kk < 8; ++kk) {
            int r = warp * 8 + kk;
            int v = (r < 32) ? ((wv0 >> r) & 1) : ((wv1 >> (r - 32)) & 1);
            float e0 = env[r * 64 + 2 * lane], e1 = env[r * 64 + 2 * lane + 1];
            float a = v ? r4.y : r4.x;
            float b = v ? r4.w : r4.z;
            float p = e0 * a + e1 * b;
            p += __shfl_xor_sync(FULLMASK, p, 1);
            p += __shfl_xor_sync(FULLMASK, p, 2);
            p += __shfl_xor_sync(FULLMASK, p, 4);
            p += __shfl_xor_sync(FULLMASK, p, 8);
            p += __shfl_xor_sync(FULLMASK, p, 16);
            if (lane == kk) {
                int grow = blockIdx.x * ROWS + r;
                if (grow < B) {
                    float lsf = 0.69314718055994531f * (float)lsx[r];
                    float m2 = fmaxf(fabsf(p), 1e-30f);
                    float pr = p / m2;
                    float ab = fmaxf(pr * pr, 1e-30f);
                    out[grow] = logf(ab) + 2.0f * (lsf + logf(m2));
                }
            }
        }
    }
}

extern "C" void kernel_launch(void* const* d_in, const int* in_sizes, int n_in,
                              void* d_out, int out_size)
{
    const int*   cfg   = (const int*)d_in[0];
    const float* left  = (const float*)d_in[1];
    const float* bulk  = (const float*)d_in[2];
    const float* right = (const float*)d_in[3];
    float* out = (float*)d_out;

    int B     = in_sizes[0] / 256;            // 8192
    int nbulk = in_sizes[2] / (64 * 2 * 64);  // 254
    int ncta  = (B + ROWS - 1) / ROWS;        // 147

    transpose_bulk<<<nbulk * 2, 256>>>(bulk);
    cudaFuncSetAttribute(mps_main, cudaFuncAttributeMaxDynamicSharedMemorySize, SMEM_BYTES);
    mps_main<<<ncta, THREADS, SMEM_BYTES>>>(cfg, left, right, out, B, nbulk);
}